// round 5
// baseline (speedup 1.0000x reference)
#include <cuda_runtime.h>

#define N_NODES 50000
#define N_EDGES 1600000
#define IN_C    128
#define HEADS   4
#define OUT_C   16
#define HC      64   // HEADS*OUT_C

// ---------------- scratch (static device globals; no allocs allowed) --------
__device__ __align__(256) float g_xw[N_NODES * HC];     // projected (256B rows)
__device__ __align__(16)  float g_asrc[N_NODES * HEADS];
__device__ __align__(16)  float g_adst[N_NODES * HEADS];
__device__ __align__(16)  int   g_cnt[N_NODES];         // in-degree histogram
__device__ __align__(16)  int   g_rowptr[N_NODES + 1];  // CSR row pointers
__device__ __align__(16)  int   g_cursor[N_NODES];      // reorder cursors
__device__ __align__(16)  int   g_ssrc[N_EDGES];        // src sorted by dst

// ---------------- K0: zero histogram ----------------------------------------
__global__ void k_zero(int n) {
    int t = blockIdx.x * blockDim.x + threadIdx.x;
    if (t < n) g_cnt[t] = 0;
}

// ---------------- K1: xw = x @ W   ([N,128]@[128,64]) -----------------------
__global__ void k_proj(const float* __restrict__ x, const float* __restrict__ W,
                       int n) {
    extern __shared__ float smem[];
    float* sW = smem;
    float* sx = smem + IN_C * HC;
    int tid = threadIdx.x;
    int row0 = blockIdx.x * 64;

    for (int i = tid; i < IN_C * HC / 4; i += 256)
        ((float4*)sW)[i] = ((const float4*)W)[i];
    for (int i = tid; i < 64 * IN_C / 4; i += 256) {
        int r = i >> 5;
        float4 v = make_float4(0.f, 0.f, 0.f, 0.f);
        if (row0 + r < n) v = ((const float4*)x)[(size_t)(row0 + r) * 32 + (i & 31)];
        ((float4*)sx)[i] = v;
    }
    __syncthreads();

    int rg = tid >> 4;
    int c4 = (tid & 15) * 4;
    unsigned long long a0[4], a1[4];
#pragma unroll
    for (int i = 0; i < 4; i++) { a0[i] = 0ull; a1[i] = 0ull; }

#pragma unroll 4
    for (int k = 0; k < IN_C; k++) {
        float4 w = *(const float4*)&sW[k * HC + c4];
        unsigned long long w01, w23;
        asm("mov.b64 %0, {%1, %2};" : "=l"(w01) : "f"(w.x), "f"(w.y));
        asm("mov.b64 %0, {%1, %2};" : "=l"(w23) : "f"(w.z), "f"(w.w));
#pragma unroll
        for (int i = 0; i < 4; i++) {
            float xv = sx[(rg * 4 + i) * IN_C + k];
            unsigned long long xp;
            asm("mov.b64 %0, {%1, %1};" : "=l"(xp) : "f"(xv));
            asm("fma.rn.f32x2 %0, %1, %2, %0;" : "+l"(a0[i]) : "l"(xp), "l"(w01));
            asm("fma.rn.f32x2 %0, %1, %2, %0;" : "+l"(a1[i]) : "l"(xp), "l"(w23));
        }
    }
#pragma unroll
    for (int i = 0; i < 4; i++) {
        int row = row0 + rg * 4 + i;
        if (row < n) {
            float4 o;
            asm("mov.b64 {%0, %1}, %2;" : "=f"(o.x), "=f"(o.y) : "l"(a0[i]));
            asm("mov.b64 {%0, %1}, %2;" : "=f"(o.z), "=f"(o.w) : "l"(a1[i]));
            *(float4*)&g_xw[row * HC + c4] = o;
        }
    }
}

// ---------------- K2: per-node attention logits -----------------------------
__global__ void k_att(const float* __restrict__ att_src,
                      const float* __restrict__ att_dst, int n) {
    int t = blockIdx.x * blockDim.x + threadIdx.x;
    if (t >= n * HEADS) return;
    int node = t >> 2, h = t & 3;
    const float4* xp = (const float4*)(g_xw + node * HC + h * OUT_C);
    const float4* as = (const float4*)(att_src + h * OUT_C);
    const float4* ad = (const float4*)(att_dst + h * OUT_C);
    float ss = 0.f, sd = 0.f;
#pragma unroll
    for (int i = 0; i < 4; i++) {
        float4 v = xp[i], a = as[i], b = ad[i];
        ss += v.x * a.x + v.y * a.y + v.z * a.z + v.w * a.w;
        sd += v.x * b.x + v.y * b.y + v.z * b.z + v.w * b.w;
    }
    g_asrc[t] = ss;
    g_adst[t] = sd;
}

// ---------------- K3: in-degree histogram ------------------------------------
__global__ void k_hist(const int* __restrict__ ei, int e) {
    int t = blockIdx.x * blockDim.x + threadIdx.x;
    if (t < e) atomicAdd(&g_cnt[ei[e + t]], 1);
}

// ---------------- K4: exclusive scan (single block, 1024 threads) -----------
__global__ void k_scan(int n, int e) {
    __shared__ int wsum[32];
    int t = threadIdx.x, lane = t & 31, wid = t >> 5;
    int chunk = (n + 1023) >> 10;
    int beg = t * chunk;
    int end = min(n, beg + chunk);
    int sum = 0;
    for (int i = beg; i < end; i++) sum += g_cnt[i];
    int v = sum;
#pragma unroll
    for (int o = 1; o < 32; o <<= 1) {
        int u = __shfl_up_sync(0xffffffffu, v, o);
        if (lane >= o) v += u;
    }
    if (lane == 31) wsum[wid] = v;
    __syncthreads();
    if (wid == 0) {
        int w = wsum[lane];
#pragma unroll
        for (int o = 1; o < 32; o <<= 1) {
            int u = __shfl_up_sync(0xffffffffu, w, o);
            if (lane >= o) w += u;
        }
        wsum[lane] = w;
    }
    __syncthreads();
    int run = v - sum + (wid > 0 ? wsum[wid - 1] : 0);
    for (int i = beg; i < end; i++) {
        int c = g_cnt[i];
        g_rowptr[i] = run;
        g_cursor[i] = run;
        run += c;
    }
    if (t == 0) g_rowptr[n] = e;
}

// ---------------- K5: reorder src by dst (minimal) ----------------------------
__global__ void k_reorder(const int* __restrict__ ei, int e) {
    int t = blockIdx.x * blockDim.x + threadIdx.x;
    if (t >= e) return;
    int s = ei[t];
    int d = ei[e + t];
    int pos = atomicAdd(&g_cursor[d], 1);
    g_ssrc[pos] = s;
}

// ---------------- K6: fused CSR aggregation + softmax + ELU + out proj ------
// Two warps per node: warp `half` handles channels [32*half, 32*half+32) =
// heads {2*half, 2*half+1}. Per 32-edge chunk: each lane computes exp for its
// OWN edge (independent gathers, batched off the critical path), then a tight
// broadcast-FMA loop: 3 shfl + sel + 1 LDG(128B) + 1 FMA + 2 FADD per edge.
__global__ void k_agg(const float* __restrict__ bias,
                      const float* __restrict__ W_out,
                      const float* __restrict__ b_out,
                      float* __restrict__ y, int n) {
    __shared__ float s_part[8];
    int warp = threadIdx.x >> 5, lane = threadIdx.x & 31;
    int node = blockIdx.x * 4 + (warp >> 1);
    int half = warp & 1;
    bool valid = node < n;
    int d = valid ? node : 0;
    int beg = g_rowptr[d];
    int end = valid ? g_rowptr[d + 1] : beg;

    int h0 = half * 2;                      // first head of this half
    float adst0 = g_adst[d * 4 + h0];
    float adst1 = g_adst[d * 4 + h0 + 1];
    int ch = half * 32 + lane;              // global channel of this lane
    int myh = lane >> 4;                    // 0 -> head h0, 1 -> head h0+1

    float acc = 0.f, exsum0 = 0.f, exsum1 = 0.f;

    for (int i = beg; i < end; i += 32) {
        int m = end - i; if (m > 32) m = 32;
        // phase 1: per-lane edge prep (independent chains, high MLP)
        int   s_l = 0;
        float ex0 = 0.f, ex1 = 0.f;
        if (lane < m) {
            s_l = g_ssrc[i + lane];
            float a0 = g_asrc[s_l * 4 + h0]     + adst0;
            float a1 = g_asrc[s_l * 4 + h0 + 1] + adst1;
            a0 = a0 > 0.f ? a0 : 0.2f * a0;
            a1 = a1 > 0.f ? a1 : 0.2f * a1;
            ex0 = __expf(a0);
            ex1 = __expf(a1);
        }
        // phase 2: broadcast + gather-FMA
#pragma unroll 4
        for (int j = 0; j < m; j++) {
            int   s  = __shfl_sync(0xffffffffu, s_l, j);
            float eA = __shfl_sync(0xffffffffu, ex0, j);
            float eB = __shfl_sync(0xffffffffu, ex1, j);
            float ev = myh ? eB : eA;
            acc += ev * g_xw[s * HC + ch];
            exsum0 += eA;
            exsum1 += eB;
        }
    }

    // normalize + bias + ELU + partial output dot
    float inv0 = 1.f / (exsum0 + 1e-16f);
    float inv1 = 1.f / (exsum1 + 1e-16f);
    float o = acc * (myh ? inv1 : inv0) + bias[ch];
    o = o > 0.f ? o : __expf(o) - 1.f;
    float p = o * W_out[ch];
#pragma unroll
    for (int off = 16; off > 0; off >>= 1)
        p += __shfl_xor_sync(0xffffffffu, p, off);
    if (lane == 0) s_part[warp] = p;
    __syncthreads();
    if (half == 0 && lane == 0 && valid)
        y[node] = s_part[warp] + s_part[warp + 1] + b_out[0];
}

// ---------------- launch -----------------------------------------------------
extern "C" void kernel_launch(void* const* d_in, const int* in_sizes, int n_in,
                              void* d_out, int out_size) {
    const float* x       = (const float*)d_in[0];
    const int*   ei      = (const int*)d_in[1];
    const float* W       = (const float*)d_in[2];
    const float* att_src = (const float*)d_in[3];
    const float* att_dst = (const float*)d_in[4];
    const float* bias    = (const float*)d_in[5];
    const float* W_out   = (const float*)d_in[6];
    const float* b_out   = (const float*)d_in[7];
    float*       y       = (float*)d_out;

    int n = in_sizes[0] / IN_C;   // 50000
    int e = in_sizes[1] / 2;      // 1600000

    const int B = 256;
    const int proj_smem = (IN_C * HC + 64 * IN_C) * (int)sizeof(float); // 64KB
    cudaFuncSetAttribute(k_proj, cudaFuncAttributeMaxDynamicSharedMemorySize,
                         proj_smem);

    k_zero<<<(n + B - 1) / B, B>>>(n);
    k_proj<<<(n + 63) / 64, 256, proj_smem>>>(x, W, n);
    k_att<<<(n * HEADS + B - 1) / B, B>>>(att_src, att_dst, n);
    k_hist<<<(e + B - 1) / B, B>>>(ei, e);
    k_scan<<<1, 1024>>>(n, e);
    k_reorder<<<(e + B - 1) / B, B>>>(ei, e);
    k_agg<<<(n + 3) / 4, 256>>>(bias, W_out, b_out, y, n);
}

// round 6
// speedup vs baseline: 1.8705x; 1.8705x over previous
#include <cuda_runtime.h>
#include <cuda_fp16.h>

#define N_NODES 50000
#define N_EDGES 1600000
#define IN_C    128
#define HEADS   4
#define OUT_C   16
#define HC      64   // HEADS*OUT_C

// ---------------- scratch (static device globals; no allocs allowed) --------
__device__ __align__(16) __half g_xwh[N_NODES * HC];    // projected, fp16
__device__ __align__(16) float  g_asrc[N_NODES * HEADS];
__device__ __align__(16) float  g_adst[N_NODES * HEADS];
__device__ __align__(16) float  g_denom[N_NODES * HEADS];
__device__ __align__(16) float  g_agg[N_NODES * HC];    // fp32 accumulators

// vectorized reduction (sm_90+): 16B atomic add, no return
__device__ __forceinline__ void red_add_v4(float* addr, float4 v) {
    asm volatile("red.global.add.v4.f32 [%0], {%1, %2, %3, %4};"
                 :: "l"(addr), "f"(v.x), "f"(v.y), "f"(v.z), "f"(v.w)
                 : "memory");
}
__device__ __forceinline__ void red_add_f32(float* addr, float v) {
    asm volatile("red.global.add.f32 [%0], %1;" :: "l"(addr), "f"(v) : "memory");
}

// ---------------- K0: zero accumulators -------------------------------------
__global__ void k_init(int n) {
    int t = blockIdx.x * blockDim.x + threadIdx.x;
    if (t < n * HC)    g_agg[t]   = 0.f;
    if (t < n * HEADS) g_denom[t] = 0.f;
}

// ---------------- K1: xw = x @ W -> fp16  ([N,128]@[128,64]) ----------------
// 256 threads, 64 rows/block. Thread = 4 rows x 4 cols, packed f32x2 FMA.
__global__ void k_proj(const float* __restrict__ x, const float* __restrict__ W,
                       int n) {
    extern __shared__ float smem[];
    float* sW = smem;              // 8192 floats
    float* sx = smem + IN_C * HC;  // 8192 floats
    int tid = threadIdx.x;
    int row0 = blockIdx.x * 64;

    for (int i = tid; i < IN_C * HC / 4; i += 256)
        ((float4*)sW)[i] = ((const float4*)W)[i];
    for (int i = tid; i < 64 * IN_C / 4; i += 256) {
        int r = i >> 5;
        float4 v = make_float4(0.f, 0.f, 0.f, 0.f);
        if (row0 + r < n) v = ((const float4*)x)[(size_t)(row0 + r) * 32 + (i & 31)];
        ((float4*)sx)[i] = v;
    }
    __syncthreads();

    int rg = tid >> 4;
    int c4 = (tid & 15) * 4;
    unsigned long long a0[4], a1[4];
#pragma unroll
    for (int i = 0; i < 4; i++) { a0[i] = 0ull; a1[i] = 0ull; }

#pragma unroll 4
    for (int k = 0; k < IN_C; k++) {
        float4 w = *(const float4*)&sW[k * HC + c4];
        unsigned long long w01, w23;
        asm("mov.b64 %0, {%1, %2};" : "=l"(w01) : "f"(w.x), "f"(w.y));
        asm("mov.b64 %0, {%1, %2};" : "=l"(w23) : "f"(w.z), "f"(w.w));
#pragma unroll
        for (int i = 0; i < 4; i++) {
            float xv = sx[(rg * 4 + i) * IN_C + k];
            unsigned long long xp;
            asm("mov.b64 %0, {%1, %1};" : "=l"(xp) : "f"(xv));
            asm("fma.rn.f32x2 %0, %1, %2, %0;" : "+l"(a0[i]) : "l"(xp), "l"(w01));
            asm("fma.rn.f32x2 %0, %1, %2, %0;" : "+l"(a1[i]) : "l"(xp), "l"(w23));
        }
    }
#pragma unroll
    for (int i = 0; i < 4; i++) {
        int row = row0 + rg * 4 + i;
        if (row < n) {
            float4 o;
            asm("mov.b64 {%0, %1}, %2;" : "=f"(o.x), "=f"(o.y) : "l"(a0[i]));
            asm("mov.b64 {%0, %1}, %2;" : "=f"(o.z), "=f"(o.w) : "l"(a1[i]));
            __half2 p0 = __floats2half2_rn(o.x, o.y);
            __half2 p1 = __floats2half2_rn(o.z, o.w);
            uint2 u;
            u.x = *(unsigned*)&p0;
            u.y = *(unsigned*)&p1;
            *(uint2*)&g_xwh[row * HC + c4] = u;
        }
    }
}

// ---------------- K2: per-node attention logits (fp16 xw) -------------------
__global__ void k_att(const float* __restrict__ att_src,
                      const float* __restrict__ att_dst, int n) {
    int t = blockIdx.x * blockDim.x + threadIdx.x;
    if (t >= n * HEADS) return;
    int node = t >> 2, h = t & 3;
    const uint4* xp = (const uint4*)(g_xwh + node * HC + h * OUT_C); // 2 x uint4
    const float* as = att_src + h * OUT_C;
    const float* ad = att_dst + h * OUT_C;
    float ss = 0.f, sd = 0.f;
#pragma unroll
    for (int u = 0; u < 2; u++) {
        uint4 q = xp[u];
        unsigned w[4] = {q.x, q.y, q.z, q.w};
#pragma unroll
        for (int k = 0; k < 4; k++) {
            float2 f = __half22float2(*(__half2*)&w[k]);
            int c = u * 8 + k * 2;
            ss += f.x * as[c] + f.y * as[c + 1];
            sd += f.x * ad[c] + f.y * ad[c + 1];
        }
    }
    g_asrc[t] = ss;
    g_adst[t] = sd;
}

// ---------------- K3: fused edge pass (fp16 gather, fp32 atomic scatter) ----
// 16 threads/edge. Thread q: head h=q>>2, channels [4q,4q+4) (8B fp16 load).
// Scatters UNNORMALIZED ex*xw[src] into agg[dst] and ex into denom[dst].
__global__ void k_edge(const int* __restrict__ ei, int e) {
    int gid = blockIdx.x * blockDim.x + threadIdx.x;
    int eid = gid >> 4;
    if (eid >= e) return;
    int q = gid & 15;
    int h = q >> 2;
    int s = __ldg(ei + eid);
    int d = __ldg(ei + e + eid);
    float a = g_asrc[s * 4 + h] + g_adst[d * 4 + h];
    a = a > 0.f ? a : 0.2f * a;
    float ex = __expf(a);
    uint2 u = *(const uint2*)&g_xwh[s * HC + q * 4];
    float2 f0 = __half22float2(*(__half2*)&u.x);
    float2 f1 = __half22float2(*(__half2*)&u.y);
    float4 v = make_float4(f0.x * ex, f0.y * ex, f1.x * ex, f1.y * ex);
    red_add_v4(g_agg + d * HC + q * 4, v);
    if ((q & 3) == 0) red_add_f32(g_denom + d * 4 + h, ex);
}

// ---------------- K4: normalize + ELU + output projection -------------------
__global__ void k_out(const float* __restrict__ bias,
                      const float* __restrict__ W_out,
                      const float* __restrict__ b_out,
                      float* __restrict__ y, int n) {
    int gid = blockIdx.x * blockDim.x + threadIdx.x;
    int node = gid >> 4;
    int q = gid & 15;
    bool valid = node < n;
    int nc = valid ? node : 0;

    float dn  = g_denom[nc * 4 + (q >> 2)];
    float inv = 1.f / (dn + 1e-16f);
    float4 a = *(const float4*)(g_agg + nc * HC + q * 4);
    float4 b = *(const float4*)(bias + q * 4);
    float4 w = *(const float4*)(W_out + q * 4);
    a.x = a.x * inv + b.x; a.y = a.y * inv + b.y;
    a.z = a.z * inv + b.z; a.w = a.w * inv + b.w;
    a.x = a.x > 0.f ? a.x : __expf(a.x) - 1.f;
    a.y = a.y > 0.f ? a.y : __expf(a.y) - 1.f;
    a.z = a.z > 0.f ? a.z : __expf(a.z) - 1.f;
    a.w = a.w > 0.f ? a.w : __expf(a.w) - 1.f;
    float p = a.x * w.x + a.y * w.y + a.z * w.z + a.w * w.w;
    p += __shfl_down_sync(0xffffffffu, p, 8, 16);
    p += __shfl_down_sync(0xffffffffu, p, 4, 16);
    p += __shfl_down_sync(0xffffffffu, p, 2, 16);
    p += __shfl_down_sync(0xffffffffu, p, 1, 16);
    if (valid && q == 0) y[node] = p + b_out[0];
}

// ---------------- launch -----------------------------------------------------
extern "C" void kernel_launch(void* const* d_in, const int* in_sizes, int n_in,
                              void* d_out, int out_size) {
    const float* x       = (const float*)d_in[0];
    const int*   ei      = (const int*)d_in[1];
    const float* W       = (const float*)d_in[2];
    const float* att_src = (const float*)d_in[3];
    const float* att_dst = (const float*)d_in[4];
    const float* bias    = (const float*)d_in[5];
    const float* W_out   = (const float*)d_in[6];
    const float* b_out   = (const float*)d_in[7];
    float*       y       = (float*)d_out;

    int n = in_sizes[0] / IN_C;   // 50000
    int e = in_sizes[1] / 2;      // 1600000

    const int B = 256;
    const int proj_smem = (IN_C * HC + 64 * IN_C) * (int)sizeof(float); // 64KB
    cudaFuncSetAttribute(k_proj, cudaFuncAttributeMaxDynamicSharedMemorySize,
                         proj_smem);

    k_init<<<(n * HC + B - 1) / B, B>>>(n);
    k_proj<<<(n + 63) / 64, 256, proj_smem>>>(x, W, n);
    k_att<<<(n * HEADS + B - 1) / B, B>>>(att_src, att_dst, n);
    k_edge<<<((size_t)e * 16 + B - 1) / B, B>>>(ei, e);
    k_out<<<(n * 16 + B - 1) / B, B>>>(bias, W_out, b_out, y, n);
}